// round 12
// baseline (speedup 1.0000x reference)
#include <cuda_runtime.h>
#include <cuda_bf16.h>
#include <cstdint>

#define NB    64          // state size
#define L     8192
#define BATCH 2048
#define QC    128         // chunk length
#define NCH   64          // chunks
#define KB    192         // 64 (X) + 128 (U)

// ---------------- constants built by setup ----------------
__device__ float d_Mf[NB * NB];                               // Ab^128
__device__ __nv_bfloat16 d_WHi[NB * QC],  d_WLo[NB * QC];     // WinT [n][i], pitch 128
__device__ __nv_bfloat16 d_PbHi[QC * KB], d_PbLo[QC * KB];    // PbT  [t][k], pitch 192
__device__ float d_V  [(size_t)NCH * BATCH * NB];             // V[j][b][n]
__device__ float d_Xst[(size_t)NCH * BATCH * NB];             // X[j][b][n]

// fp64 setup workspace
__device__ double d_T[NB * NB], d_R[NB * NB], d_X[NB * NB], d_X2[NB * NB];
__device__ double d_W[NB * NB], d_Ab[NB * NB], d_SA[NB * NB], d_SB[NB * NB];
__device__ double d_Rm[QC + 1][NB], d_Cm[QC][NB], d_Kk[QC];
__device__ double d_Cv[NB], d_Bv[NB], d_Dv, d_sp;
__device__ unsigned g_cnt = 0;
__device__ volatile unsigned g_gen = 0;

// ---------------- helpers ----------------
__device__ __forceinline__ void splitpk(float a, float b, uint32_t& hi, uint32_t& lo) {
    __nv_bfloat16 ha = __float2bfloat16(a), hb = __float2bfloat16(b);
    __nv_bfloat162 h, l;
    h.x = ha; h.y = hb;
    l.x = __float2bfloat16(a - __bfloat162float(ha));
    l.y = __float2bfloat16(b - __bfloat162float(hb));
    hi = *(uint32_t*)&h; lo = *(uint32_t*)&l;
}
__device__ __forceinline__ void mma16816(float* c, uint32_t a0, uint32_t a1,
                                         uint32_t a2, uint32_t a3,
                                         uint32_t b0, uint32_t b1) {
    asm volatile(
        "mma.sync.aligned.m16n8k16.row.col.f32.bf16.bf16.f32 "
        "{%0,%1,%2,%3}, {%4,%5,%6,%7}, {%8,%9}, {%0,%1,%2,%3};"
        : "+f"(c[0]), "+f"(c[1]), "+f"(c[2]), "+f"(c[3])
        : "r"(a0), "r"(a1), "r"(a2), "r"(a3), "r"(b0), "r"(b1));
}
__device__ __forceinline__ double dot64_row(const double* v, const double* S, int t) {
    double a0 = 0, a1 = 0, a2 = 0, a3 = 0;
    #pragma unroll 8
    for (int m = 0; m < 64; m += 4) {
        a0 += v[m]     * S[m * 64 + t];
        a1 += v[m + 1] * S[(m + 1) * 64 + t];
        a2 += v[m + 2] * S[(m + 2) * 64 + t];
        a3 += v[m + 3] * S[(m + 3) * 64 + t];
    }
    return (a0 + a1) + (a2 + a3);
}
__device__ __forceinline__ double dot64_col(const double* S, int t, const double* v) {
    double a0 = 0, a1 = 0, a2 = 0, a3 = 0;
    #pragma unroll 8
    for (int m = 0; m < 64; m += 4) {
        a0 += S[t * 64 + m]     * v[m];
        a1 += S[t * 64 + m + 1] * v[m + 1];
        a2 += S[t * 64 + m + 2] * v[m + 2];
        a3 += S[t * 64 + m + 3] * v[m + 3];
    }
    return (a0 + a1) + (a2 + a3);
}

// ---------------- L0: fp32 Gauss-Jordan seed + fp64 stash ----------------
__global__ void ssm_gj(const float* __restrict__ A, const float* __restrict__ B,
                       const float* __restrict__ C, const float* __restrict__ Dp,
                       const float* __restrict__ ls) {
    __shared__ float G[64 * 128];
    __shared__ float fac[64];
    const int tid = threadIdx.x, nt = 256;
    const double sd = exp((double)ls[0]);
    const float s = (float)sd;
    for (int i = tid; i < 4096; i += nt) {
        int r = i >> 6, c = i & 63;
        double a = (double)A[i];
        d_T[i] = (r == c ? 1.0 : 0.0) - 0.5 * sd * a;
        d_R[i] = (r == c ? 1.0 : 0.0) + 0.5 * sd * a;
    }
    for (int i = tid; i < 8192; i += nt) {
        int r = i >> 7, c = i & 127;
        G[i] = (c < 64) ? ((r == c ? 1.f : 0.f) - 0.5f * s * A[r * 64 + c])
                        : (((c - 64) == r) ? 1.f : 0.f);
    }
    if (tid < 64) { d_Cv[tid] = (double)C[tid]; d_Bv[tid] = (double)B[tid]; }
    if (tid == 0) { d_Dv = (double)Dp[0]; d_sp = sd; }
    __syncthreads();
    for (int p = 0; p < 64; ++p) {
        float pv = 1.f / G[p * 128 + p];
        __syncthreads();
        for (int c = tid; c < 128; c += nt) G[p * 128 + c] *= pv;
        for (int r = tid; r < 64; r += nt) fac[r] = G[r * 128 + p];
        __syncthreads();
        for (int i = tid; i < 8192; i += nt) {
            int r = i >> 7, c = i & 127;
            if (r != p) G[i] -= fac[r] * G[p * 128 + c];
        }
        __syncthreads();
    }
    for (int i = tid; i < 4096; i += nt)
        d_X[i] = (double)G[(i >> 6) * 128 + 64 + (i & 63)];
}

// ---------------- L1: mega setup (192 blocks x 64, grid barrier) ----------
__device__ __forceinline__ void gbar() {
    __syncthreads();
    if (threadIdx.x == 0) {
        __threadfence();
        unsigned g = g_gen;
        if (atomicAdd(&g_cnt, 1u) == 191u) { g_cnt = 0; __threadfence(); g_gen = g + 1; }
        else { while (g_gen == g) __nanosleep(64); __threadfence(); }
    }
    __syncthreads();
}
__global__ void ssm_mega() {
    __shared__ double v[64], red[64];
    const int b = blockIdx.x, t = threadIdx.x;
    if (b < 64) {                                  // W = X*T
        v[t] = d_X[b * 64 + t]; __syncthreads();
        d_W[b * 64 + t] = dot64_row(v, d_T, t);
    }
    gbar();
    if (b < 64) {                                  // X2 = 2X - W*X  (Newton)
        v[t] = d_W[b * 64 + t]; __syncthreads();
        d_X2[b * 64 + t] = 2.0 * d_X[b * 64 + t] - dot64_row(v, d_X, t);
    }
    gbar();
    if (b < 64) {                                  // Ab = X2*R
        v[t] = d_X2[b * 64 + t]; __syncthreads();
        d_Ab[b * 64 + t] = dot64_row(v, d_R, t);
    } else if (b == 64) {                          // Bb; seeds
        v[t] = d_Bv[t]; __syncthreads();
        d_Cm[0][t] = d_sp * dot64_col(d_X2, t, v);
        d_Rm[0][t] = d_Cv[t];
    }
    gbar();
    for (int lev = 0; lev < 7; ++lev) {            // chains + squaring to Ab^128
        int tw = 1 << lev;
        const double* S = (lev == 0) ? d_Ab : ((lev & 1) ? d_SA : d_SB);
        double* Sd = (lev & 1) ? d_SB : d_SA;
        if (b < tw) {
            v[t] = d_Rm[b][t]; __syncthreads();
            d_Rm[b + tw][t] = dot64_row(v, S, t);
        } else if (b < 2 * tw) {
            v[t] = d_Cm[b - tw][t]; __syncthreads();
            d_Cm[b][t] = dot64_col(S, t, v);
        } else if (b < 2 * tw + 64) {
            int r = b - 2 * tw;
            v[t] = S[r * 64 + t]; __syncthreads();
            Sd[r * 64 + t] = dot64_row(v, S, t);
        }
        gbar();
    }
    // M = Ab^128 lives in d_SA
    if (b < QC) {                                  // Kk[b] = C . c_b  (+D at 0)
        red[t] = d_Cv[t] * d_Cm[b][t]; __syncthreads();
        for (int o = 32; o > 0; o >>= 1) { if (t < o) red[t] += red[t + o]; __syncthreads(); }
        if (t == 0) d_Kk[b] = red[0] + ((b == 0) ? d_Dv : 0.0);
    } else if (b == QC) {                          // r_128 = C * M
        v[t] = d_Cv[t]; __syncthreads();
        d_Rm[QC][t] = dot64_row(v, d_SA, t);
    }
    gbar();
    const int gt = b * 64 + t, NT = 192 * 64;      // fills
    for (int i = gt; i < 4096; i += NT) d_Mf[i] = (float)d_SA[i];
    for (int i = gt; i < NB * QC; i += NT) {       // WinT[n][ii] = c_{127-ii}[n]
        int n = i >> 7, ii = i & 127;
        float f = (float)d_Cm[QC - 1 - ii][n];
        __nv_bfloat16 h = __float2bfloat16(f);
        d_WHi[i] = h; d_WLo[i] = __float2bfloat16(f - __bfloat162float(h));
    }
    for (int i = gt; i < QC * KB; i += NT) {       // PbT[t][k]
        int tt = i / KB, k = i % KB;
        double dv;
        if (k < 64) dv = d_Rm[tt + 1][k];
        else { int ii = k - 64; dv = (ii <= tt) ? d_Kk[tt - ii] : 0.0; }
        float f = (float)dv;
        __nv_bfloat16 h = __float2bfloat16(f);
        d_PbHi[i] = h; d_PbLo[i] = __float2bfloat16(f - __bfloat162float(h));
    }
}

// ---------------- A0: V = U * Win  (1024 CTAs x 256, HMMA, single stage) ---
// u32 layout, pitch 68: AH [128][68], AL, BH [64][68], BL.  Total 104448 B.
#define A0_AH 0
#define A0_AL 8704
#define A0_BH 17408
#define A0_BL 21760
__global__ void __launch_bounds__(256) ssm_a0(const float* __restrict__ u) {
    extern __shared__ __align__(16) uint32_t sw[];
    const int tid = threadIdx.x;
    const int j = blockIdx.x >> 4, b0 = (blockIdx.x & 15) << 7;
    const int wid = tid >> 5, lane = tid & 31;
    const int g = lane >> 2, tq = lane & 3;
    const int wm = wid >> 1, wn = wid & 1;          // 4x2 warp grid
    const int RM = wm * 32, CN = wn * 32;

    // fill Win (64 rows x 64 u32)
    for (int i = tid; i < 4096; i += 256) {
        int n = i >> 6, c = i & 63;
        sw[A0_BH + n * 68 + c] = ((const uint32_t*)d_WHi)[i];
        sw[A0_BL + n * 68 + c] = ((const uint32_t*)d_WLo)[i];
    }
    // fill U (128 rows x 128 floats -> 64 u32 hi/lo)
    for (int i = tid; i < 4096; i += 256) {
        int r = i >> 5, q = (i & 31) * 4;
        float4 f = *(const float4*)(u + (size_t)(b0 + r) * L + j * QC + q);
        uint32_t h0, l0, h1, l1;
        splitpk(f.x, f.y, h0, l0); splitpk(f.z, f.w, h1, l1);
        int o = r * 68 + (q >> 1);
        sw[A0_AH + o] = h0; sw[A0_AH + o + 1] = h1;
        sw[A0_AL + o] = l0; sw[A0_AL + o + 1] = l1;
    }
    __syncthreads();

    float acc[2][4][4];
    #pragma unroll
    for (int a = 0; a < 2; ++a)
        #pragma unroll
        for (int bq = 0; bq < 4; ++bq)
            #pragma unroll
            for (int cq = 0; cq < 4; ++cq) acc[a][bq][cq] = 0.f;

    #pragma unroll
    for (int it = 0; it < 8; ++it) {
        const int kb = it * 8 + tq;
        uint32_t bh0[4], bh1[4], bl0[4], bl1[4];
        #pragma unroll
        for (int nt = 0; nt < 4; ++nt) {
            int n = CN + nt * 8 + g;
            bh0[nt] = sw[A0_BH + n * 68 + kb];
            bh1[nt] = sw[A0_BH + n * 68 + kb + 4];
            bl0[nt] = sw[A0_BL + n * 68 + kb];
            bl1[nt] = sw[A0_BL + n * 68 + kb + 4];
        }
        #pragma unroll
        for (int mt = 0; mt < 2; ++mt) {
            int r0 = RM + mt * 16 + g, r1 = r0 + 8;
            uint32_t ah0 = sw[A0_AH + r0 * 68 + kb];
            uint32_t ah1 = sw[A0_AH + r1 * 68 + kb];
            uint32_t ah2 = sw[A0_AH + r0 * 68 + kb + 4];
            uint32_t ah3 = sw[A0_AH + r1 * 68 + kb + 4];
            uint32_t al0 = sw[A0_AL + r0 * 68 + kb];
            uint32_t al1 = sw[A0_AL + r1 * 68 + kb];
            uint32_t al2 = sw[A0_AL + r0 * 68 + kb + 4];
            uint32_t al3 = sw[A0_AL + r1 * 68 + kb + 4];
            #pragma unroll
            for (int nt = 0; nt < 4; ++nt) {
                mma16816(acc[mt][nt], ah0, ah1, ah2, ah3, bh0[nt], bh1[nt]);
                mma16816(acc[mt][nt], ah0, ah1, ah2, ah3, bl0[nt], bl1[nt]);
                mma16816(acc[mt][nt], al0, al1, al2, al3, bh0[nt], bh1[nt]);
            }
        }
    }
    #pragma unroll
    for (int mt = 0; mt < 2; ++mt) {
        #pragma unroll
        for (int nt = 0; nt < 4; ++nt) {
            int r0 = RM + mt * 16 + g, c = CN + nt * 8 + tq * 2;
            float* vp = d_V + ((size_t)j * BATCH + b0) * NB;
            *(float2*)(vp + (size_t)r0 * NB + c)       = make_float2(acc[mt][nt][0], acc[mt][nt][1]);
            *(float2*)(vp + (size_t)(r0 + 8) * NB + c) = make_float2(acc[mt][nt][2], acc[mt][nt][3]);
        }
    }
}

// ---------------- A1: sequential scan (256 CTAs x 128, fp32) ---------------
// Double-buffered Xs, ONE barrier per step, register-held X_j, V prefetch.
__global__ void __launch_bounds__(128) ssm_a1() {
    __shared__ float MsT[4096];      // [n][c] = Mf[c][n]
    __shared__ float Xs[2][512];     // [buf][row][n]
    const int tid = threadIdx.x;
    const int rowBase = blockIdx.x * 8;
    for (int i = tid; i < 4096; i += 128) MsT[i] = d_Mf[(i & 63) * 64 + (i >> 6)];
    for (int i = tid; i < 512; i += 128) Xs[0][i] = 0.f;
    __syncthreads();
    const int row = tid >> 4, c0 = (tid & 15) * 4;
    const size_t gstride = (size_t)BATCH * NB;
    float* xst = d_Xst + ((size_t)rowBase + row) * NB + c0;
    const float* vsrc = d_V + ((size_t)rowBase + row) * NB + c0;

    float4 xcur = make_float4(0.f, 0.f, 0.f, 0.f);          // X_0
    float4 vnext = *(const float4*)(vsrc);                  // V_0

    for (int j = 0; j < NCH; ++j) {
        *(float4*)(xst + (size_t)j * gstride) = xcur;       // store X_j
        if (j == NCH - 1) break;
        const float4 vcur = vnext;
        if (j < NCH - 2)
            vnext = *(const float4*)(vsrc + (size_t)(j + 1) * gstride);
        const float* xrow = Xs[j & 1] + row * 64;
        float a0 = vcur.x, a1 = vcur.y, a2 = vcur.z, a3 = vcur.w;
        #pragma unroll
        for (int n = 0; n < 64; ++n) {
            float xv = xrow[n];
            float4 m = *(const float4*)(MsT + n * 64 + c0);
            a0 += xv * m.x; a1 += xv * m.y; a2 += xv * m.z; a3 += xv * m.w;
        }
        xcur = make_float4(a0, a1, a2, a3);
        *(float4*)(Xs[(j + 1) & 1] + row * 64 + c0) = xcur;
        __syncthreads();
    }
}

// ---------------- B: Y = [X|U] * PbT  (1024 CTAs x 256, single stage) ------
// u32 layout, pitch 100: AH [128][100], AL, BH [128][100], BL. Total 204800 B.
#define B_AH 0
#define B_AL 12800
#define B_BH 25600
#define B_BL 38400
__global__ void __launch_bounds__(256) ssm_b(const float* __restrict__ u,
                                             float* __restrict__ y) {
    extern __shared__ __align__(16) uint32_t sw[];
    const int tid = threadIdx.x;
    const int j = blockIdx.x >> 4, b0 = (blockIdx.x & 15) << 7;
    const int wid = tid >> 5, lane = tid & 31;
    const int g = lane >> 2, tq = lane & 3;
    const int wm = wid >> 2, wn = wid & 3;          // 2x4 warp grid
    const int RM = wm * 64, CN = wn * 32;

    // fill PbT (128 rows x 96 u32)
    for (int i = tid; i < 12288; i += 256) {
        int r = i / 96, c = i - r * 96;
        sw[B_BH + r * 100 + c] = ((const uint32_t*)d_PbHi)[i];
        sw[B_BL + r * 100 + c] = ((const uint32_t*)d_PbLo)[i];
    }
    // fill A: X part (k u32 0..31)
    for (int i = tid; i < 2048; i += 256) {
        int r = i >> 4, c4 = (i & 15) * 4;
        float4 f = *(const float4*)(d_Xst + ((size_t)j * BATCH + b0 + r) * NB + c4);
        uint32_t h0, l0, h1, l1;
        splitpk(f.x, f.y, h0, l0); splitpk(f.z, f.w, h1, l1);
        int o = r * 100 + (c4 >> 1);
        sw[B_AH + o] = h0; sw[B_AH + o + 1] = h1;
        sw[B_AL + o] = l0; sw[B_AL + o + 1] = l1;
    }
    // fill A: U part (k u32 32..95)
    for (int i = tid; i < 4096; i += 256) {
        int r = i >> 5, q = (i & 31) * 4;
        float4 f = *(const float4*)(u + (size_t)(b0 + r) * L + j * QC + q);
        uint32_t h0, l0, h1, l1;
        splitpk(f.x, f.y, h0, l0); splitpk(f.z, f.w, h1, l1);
        int o = r * 100 + 32 + (q >> 1);
        sw[B_AH + o] = h0; sw[B_AH + o + 1] = h1;
        sw[B_AL + o] = l0; sw[B_AL + o + 1] = l1;
    }
    __syncthreads();

    float acc[4][4][4];
    #pragma unroll
    for (int a = 0; a < 4; ++a)
        #pragma unroll
        for (int bq = 0; bq < 4; ++bq)
            #pragma unroll
            for (int cq = 0; cq < 4; ++cq) acc[a][bq][cq] = 0.f;

    #pragma unroll 4
    for (int it = 0; it < 12; ++it) {
        const int kb = it * 8 + tq;
        uint32_t bh0[4], bh1[4], bl0[4], bl1[4];
        #pragma unroll
        for (int nt = 0; nt < 4; ++nt) {
            int n = CN + nt * 8 + g;
            bh0[nt] = sw[B_BH + n * 100 + kb];
            bh1[nt] = sw[B_BH + n * 100 + kb + 4];
            bl0[nt] = sw[B_BL + n * 100 + kb];
            bl1[nt] = sw[B_BL + n * 100 + kb + 4];
        }
        #pragma unroll
        for (int mt = 0; mt < 4; ++mt) {
            int r0 = RM + mt * 16 + g, r1 = r0 + 8;
            uint32_t ah0 = sw[B_AH + r0 * 100 + kb];
            uint32_t ah1 = sw[B_AH + r1 * 100 + kb];
            uint32_t ah2 = sw[B_AH + r0 * 100 + kb + 4];
            uint32_t ah3 = sw[B_AH + r1 * 100 + kb + 4];
            uint32_t al0 = sw[B_AL + r0 * 100 + kb];
            uint32_t al1 = sw[B_AL + r1 * 100 + kb];
            uint32_t al2 = sw[B_AL + r0 * 100 + kb + 4];
            uint32_t al3 = sw[B_AL + r1 * 100 + kb + 4];
            #pragma unroll
            for (int nt = 0; nt < 4; ++nt) {
                mma16816(acc[mt][nt], ah0, ah1, ah2, ah3, bh0[nt], bh1[nt]);
                mma16816(acc[mt][nt], ah0, ah1, ah2, ah3, bl0[nt], bl1[nt]);
                mma16816(acc[mt][nt], al0, al1, al2, al3, bh0[nt], bh1[nt]);
            }
        }
    }
    #pragma unroll
    for (int mt = 0; mt < 4; ++mt) {
        #pragma unroll
        for (int nt = 0; nt < 4; ++nt) {
            int r0 = RM + mt * 16 + g;
            int col = j * QC + CN + nt * 8 + tq * 2;
            *(float2*)(y + (size_t)(b0 + r0) * L + col)     = make_float2(acc[mt][nt][0], acc[mt][nt][1]);
            *(float2*)(y + (size_t)(b0 + r0 + 8) * L + col) = make_float2(acc[mt][nt][2], acc[mt][nt][3]);
        }
    }
}

extern "C" void kernel_launch(void* const* d_in, const int* in_sizes, int n_in,
                              void* d_out, int out_size) {
    const float* u  = (const float*)d_in[0];
    const float* A  = (const float*)d_in[1];
    const float* B  = (const float*)d_in[2];
    const float* C  = (const float*)d_in[3];
    const float* D  = (const float*)d_in[4];
    const float* ls = (const float*)d_in[5];
    float* y = (float*)d_out;

    const int smA0 = 104448;
    const int smB  = 204800;
    cudaFuncSetAttribute(ssm_a0, cudaFuncAttributeMaxDynamicSharedMemorySize, smA0);
    cudaFuncSetAttribute(ssm_b,  cudaFuncAttributeMaxDynamicSharedMemorySize, smB);

    ssm_gj<<<1, 256>>>(A, B, C, D, ls);
    ssm_mega<<<192, 64>>>();
    ssm_a0<<<1024, 256, smA0>>>(u);
    ssm_a1<<<256, 128>>>();
    ssm_b<<<1024, 256, smB>>>(u, y);
}

// round 13
// speedup vs baseline: 1.0116x; 1.0116x over previous
#include <cuda_runtime.h>
#include <cuda_bf16.h>
#include <cstdint>

#define NB    64          // state size
#define L     8192
#define BATCH 2048
#define QC    128         // chunk length
#define NCH   64          // chunks
#define KB    192         // 64 (X) + 128 (U)

// ---------------- constants built by setup ----------------
__device__ float d_Mf[NB * NB];                               // Ab^128
__device__ __nv_bfloat16 d_WHi[NB * QC],  d_WLo[NB * QC];     // WinT [n][i], pitch 128
__device__ __nv_bfloat16 d_PbHi[QC * KB], d_PbLo[QC * KB];    // PbT  [t][k], pitch 192
__device__ float d_V  [(size_t)NCH * BATCH * NB];             // V[j][b][n]
__device__ float d_Xst[(size_t)NCH * BATCH * NB];             // X[j][b][n]

// fp64 setup workspace
__device__ double d_T[NB * NB], d_R[NB * NB], d_X[NB * NB], d_X2[NB * NB];
__device__ double d_W[NB * NB], d_Ab[NB * NB], d_SA[NB * NB], d_SB[NB * NB];
__device__ double d_Rm[QC + 1][NB], d_Cm[QC][NB], d_Kk[QC];
__device__ double d_Cv[NB], d_Bv[NB], d_Dv, d_sp;
__device__ unsigned g_cnt = 0;
__device__ volatile unsigned g_gen = 0;

// ---------------- helpers ----------------
__device__ __forceinline__ void splitpk(float a, float b, uint32_t& hi, uint32_t& lo) {
    __nv_bfloat16 ha = __float2bfloat16(a), hb = __float2bfloat16(b);
    __nv_bfloat162 h, l;
    h.x = ha; h.y = hb;
    l.x = __float2bfloat16(a - __bfloat162float(ha));
    l.y = __float2bfloat16(b - __bfloat162float(hb));
    hi = *(uint32_t*)&h; lo = *(uint32_t*)&l;
}
__device__ __forceinline__ void mma16816(float* c, uint32_t a0, uint32_t a1,
                                         uint32_t a2, uint32_t a3,
                                         uint32_t b0, uint32_t b1) {
    asm volatile(
        "mma.sync.aligned.m16n8k16.row.col.f32.bf16.bf16.f32 "
        "{%0,%1,%2,%3}, {%4,%5,%6,%7}, {%8,%9}, {%0,%1,%2,%3};"
        : "+f"(c[0]), "+f"(c[1]), "+f"(c[2]), "+f"(c[3])
        : "r"(a0), "r"(a1), "r"(a2), "r"(a3), "r"(b0), "r"(b1));
}
__device__ __forceinline__ double dot64_row(const double* v, const double* S, int t) {
    double a0 = 0, a1 = 0, a2 = 0, a3 = 0;
    #pragma unroll 8
    for (int m = 0; m < 64; m += 4) {
        a0 += v[m]     * S[m * 64 + t];
        a1 += v[m + 1] * S[(m + 1) * 64 + t];
        a2 += v[m + 2] * S[(m + 2) * 64 + t];
        a3 += v[m + 3] * S[(m + 3) * 64 + t];
    }
    return (a0 + a1) + (a2 + a3);
}
__device__ __forceinline__ double dot64_col(const double* S, int t, const double* v) {
    double a0 = 0, a1 = 0, a2 = 0, a3 = 0;
    #pragma unroll 8
    for (int m = 0; m < 64; m += 4) {
        a0 += S[t * 64 + m]     * v[m];
        a1 += S[t * 64 + m + 1] * v[m + 1];
        a2 += S[t * 64 + m + 2] * v[m + 2];
        a3 += S[t * 64 + m + 3] * v[m + 3];
    }
    return (a0 + a1) + (a2 + a3);
}

// ---------------- L0: fp32 Gauss-Jordan seed + fp64 stash ----------------
__global__ void ssm_gj(const float* __restrict__ A, const float* __restrict__ B,
                       const float* __restrict__ C, const float* __restrict__ Dp,
                       const float* __restrict__ ls) {
    __shared__ float G[64 * 128];
    __shared__ float fac[64];
    const int tid = threadIdx.x, nt = 256;
    const double sd = exp((double)ls[0]);
    const float s = (float)sd;
    for (int i = tid; i < 4096; i += nt) {
        int r = i >> 6, c = i & 63;
        double a = (double)A[i];
        d_T[i] = (r == c ? 1.0 : 0.0) - 0.5 * sd * a;
        d_R[i] = (r == c ? 1.0 : 0.0) + 0.5 * sd * a;
    }
    for (int i = tid; i < 8192; i += nt) {
        int r = i >> 7, c = i & 127;
        G[i] = (c < 64) ? ((r == c ? 1.f : 0.f) - 0.5f * s * A[r * 64 + c])
                        : (((c - 64) == r) ? 1.f : 0.f);
    }
    if (tid < 64) { d_Cv[tid] = (double)C[tid]; d_Bv[tid] = (double)B[tid]; }
    if (tid == 0) { d_Dv = (double)Dp[0]; d_sp = sd; }
    __syncthreads();
    for (int p = 0; p < 64; ++p) {
        float pv = 1.f / G[p * 128 + p];
        __syncthreads();
        for (int c = tid; c < 128; c += nt) G[p * 128 + c] *= pv;
        for (int r = tid; r < 64; r += nt) fac[r] = G[r * 128 + p];
        __syncthreads();
        for (int i = tid; i < 8192; i += nt) {
            int r = i >> 7, c = i & 127;
            if (r != p) G[i] -= fac[r] * G[p * 128 + c];
        }
        __syncthreads();
    }
    for (int i = tid; i < 4096; i += nt)
        d_X[i] = (double)G[(i >> 6) * 128 + 64 + (i & 63)];
}

// ---------------- L1: mega setup (192 blocks x 64, grid barrier) ----------
__device__ __forceinline__ void gbar() {
    __syncthreads();
    if (threadIdx.x == 0) {
        __threadfence();
        unsigned g = g_gen;
        if (atomicAdd(&g_cnt, 1u) == 191u) { g_cnt = 0; __threadfence(); g_gen = g + 1; }
        else { while (g_gen == g) __nanosleep(64); __threadfence(); }
    }
    __syncthreads();
}
__global__ void ssm_mega() {
    __shared__ double v[64], red[64];
    const int b = blockIdx.x, t = threadIdx.x;
    if (b < 64) {                                  // W = X*T
        v[t] = d_X[b * 64 + t]; __syncthreads();
        d_W[b * 64 + t] = dot64_row(v, d_T, t);
    }
    gbar();
    if (b < 64) {                                  // X2 = 2X - W*X  (Newton)
        v[t] = d_W[b * 64 + t]; __syncthreads();
        d_X2[b * 64 + t] = 2.0 * d_X[b * 64 + t] - dot64_row(v, d_X, t);
    }
    gbar();
    if (b < 64) {                                  // Ab = X2*R
        v[t] = d_X2[b * 64 + t]; __syncthreads();
        d_Ab[b * 64 + t] = dot64_row(v, d_R, t);
    } else if (b == 64) {                          // Bb; seeds
        v[t] = d_Bv[t]; __syncthreads();
        d_Cm[0][t] = d_sp * dot64_col(d_X2, t, v);
        d_Rm[0][t] = d_Cv[t];
    }
    gbar();
    for (int lev = 0; lev < 7; ++lev) {            // chains + squaring to Ab^128
        int tw = 1 << lev;
        const double* S = (lev == 0) ? d_Ab : ((lev & 1) ? d_SA : d_SB);
        double* Sd = (lev & 1) ? d_SB : d_SA;
        if (b < tw) {
            v[t] = d_Rm[b][t]; __syncthreads();
            d_Rm[b + tw][t] = dot64_row(v, S, t);
        } else if (b < 2 * tw) {
            v[t] = d_Cm[b - tw][t]; __syncthreads();
            d_Cm[b][t] = dot64_col(S, t, v);
        } else if (b < 2 * tw + 64) {
            int r = b - 2 * tw;
            v[t] = S[r * 64 + t]; __syncthreads();
            Sd[r * 64 + t] = dot64_row(v, S, t);
        }
        gbar();
    }
    // M = Ab^128 lives in d_SA
    if (b < QC) {                                  // Kk[b] = C . c_b  (+D at 0)
        red[t] = d_Cv[t] * d_Cm[b][t]; __syncthreads();
        for (int o = 32; o > 0; o >>= 1) { if (t < o) red[t] += red[t + o]; __syncthreads(); }
        if (t == 0) d_Kk[b] = red[0] + ((b == 0) ? d_Dv : 0.0);
    } else if (b == QC) {                          // r_128 = C * M
        v[t] = d_Cv[t]; __syncthreads();
        d_Rm[QC][t] = dot64_row(v, d_SA, t);
    }
    gbar();
    const int gt = b * 64 + t, NT = 192 * 64;      // fills
    for (int i = gt; i < 4096; i += NT) d_Mf[i] = (float)d_SA[i];
    for (int i = gt; i < NB * QC; i += NT) {       // WinT[n][ii] = c_{127-ii}[n]
        int n = i >> 7, ii = i & 127;
        float f = (float)d_Cm[QC - 1 - ii][n];
        __nv_bfloat16 h = __float2bfloat16(f);
        d_WHi[i] = h; d_WLo[i] = __float2bfloat16(f - __bfloat162float(h));
    }
    for (int i = gt; i < QC * KB; i += NT) {       // PbT[t][k]
        int tt = i / KB, k = i % KB;
        double dv;
        if (k < 64) dv = d_Rm[tt + 1][k];
        else { int ii = k - 64; dv = (ii <= tt) ? d_Kk[tt - ii] : 0.0; }
        float f = (float)dv;
        __nv_bfloat16 h = __float2bfloat16(f);
        d_PbHi[i] = h; d_PbLo[i] = __float2bfloat16(f - __bfloat162float(h));
    }
}

// ---------------- A0: V = U * Win  (1024 CTAs x 256, HMMA, single stage) ---
// u32 layout, pitch 68: AH [128][68], AL, BH [64][68], BL.  Total 104448 B.
#define A0_AH 0
#define A0_AL 8704
#define A0_BH 17408
#define A0_BL 21760
__global__ void __launch_bounds__(256) ssm_a0(const float* __restrict__ u) {
    extern __shared__ __align__(16) uint32_t sw[];
    const int tid = threadIdx.x;
    const int j = blockIdx.x >> 4, b0 = (blockIdx.x & 15) << 7;
    const int wid = tid >> 5, lane = tid & 31;
    const int g = lane >> 2, tq = lane & 3;
    const int wm = wid >> 1, wn = wid & 1;          // 4x2 warp grid
    const int RM = wm * 32, CN = wn * 32;

    // fill Win (64 rows x 64 u32)
    for (int i = tid; i < 4096; i += 256) {
        int n = i >> 6, c = i & 63;
        sw[A0_BH + n * 68 + c] = ((const uint32_t*)d_WHi)[i];
        sw[A0_BL + n * 68 + c] = ((const uint32_t*)d_WLo)[i];
    }
    // fill U (128 rows x 128 floats -> 64 u32 hi/lo)
    for (int i = tid; i < 4096; i += 256) {
        int r = i >> 5, q = (i & 31) * 4;
        float4 f = *(const float4*)(u + (size_t)(b0 + r) * L + j * QC + q);
        uint32_t h0, l0, h1, l1;
        splitpk(f.x, f.y, h0, l0); splitpk(f.z, f.w, h1, l1);
        int o = r * 68 + (q >> 1);
        sw[A0_AH + o] = h0; sw[A0_AH + o + 1] = h1;
        sw[A0_AL + o] = l0; sw[A0_AL + o + 1] = l1;
    }
    __syncthreads();

    float acc[2][4][4];
    #pragma unroll
    for (int a = 0; a < 2; ++a)
        #pragma unroll
        for (int bq = 0; bq < 4; ++bq)
            #pragma unroll
            for (int cq = 0; cq < 4; ++cq) acc[a][bq][cq] = 0.f;

    #pragma unroll
    for (int it = 0; it < 8; ++it) {
        const int kb = it * 8 + tq;
        uint32_t bh0[4], bh1[4], bl0[4], bl1[4];
        #pragma unroll
        for (int nt = 0; nt < 4; ++nt) {
            int n = CN + nt * 8 + g;
            bh0[nt] = sw[A0_BH + n * 68 + kb];
            bh1[nt] = sw[A0_BH + n * 68 + kb + 4];
            bl0[nt] = sw[A0_BL + n * 68 + kb];
            bl1[nt] = sw[A0_BL + n * 68 + kb + 4];
        }
        #pragma unroll
        for (int mt = 0; mt < 2; ++mt) {
            int r0 = RM + mt * 16 + g, r1 = r0 + 8;
            uint32_t ah0 = sw[A0_AH + r0 * 68 + kb];
            uint32_t ah1 = sw[A0_AH + r1 * 68 + kb];
            uint32_t ah2 = sw[A0_AH + r0 * 68 + kb + 4];
            uint32_t ah3 = sw[A0_AH + r1 * 68 + kb + 4];
            uint32_t al0 = sw[A0_AL + r0 * 68 + kb];
            uint32_t al1 = sw[A0_AL + r1 * 68 + kb];
            uint32_t al2 = sw[A0_AL + r0 * 68 + kb + 4];
            uint32_t al3 = sw[A0_AL + r1 * 68 + kb + 4];
            #pragma unroll
            for (int nt = 0; nt < 4; ++nt) {
                mma16816(acc[mt][nt], ah0, ah1, ah2, ah3, bh0[nt], bh1[nt]);
                mma16816(acc[mt][nt], ah0, ah1, ah2, ah3, bl0[nt], bl1[nt]);
                mma16816(acc[mt][nt], al0, al1, al2, al3, bh0[nt], bh1[nt]);
            }
        }
    }
    #pragma unroll
    for (int mt = 0; mt < 2; ++mt) {
        #pragma unroll
        for (int nt = 0; nt < 4; ++nt) {
            int r0 = RM + mt * 16 + g, c = CN + nt * 8 + tq * 2;
            float* vp = d_V + ((size_t)j * BATCH + b0) * NB;
            *(float2*)(vp + (size_t)r0 * NB + c)       = make_float2(acc[mt][nt][0], acc[mt][nt][1]);
            *(float2*)(vp + (size_t)(r0 + 8) * NB + c) = make_float2(acc[mt][nt][2], acc[mt][nt][3]);
        }
    }
}

// ---------------- A1: sequential scan (256 CTAs x 128, fp32) ---------------
// Double-buffered Xs, ONE barrier per step, register-held X_j, V prefetch.
__global__ void __launch_bounds__(128) ssm_a1() {
    __shared__ float MsT[4096];      // [n][c] = Mf[c][n]
    __shared__ float Xs[2][512];     // [buf][row][n]
    const int tid = threadIdx.x;
    const int rowBase = blockIdx.x * 8;
    for (int i = tid; i < 4096; i += 128) MsT[i] = d_Mf[(i & 63) * 64 + (i >> 6)];
    for (int i = tid; i < 512; i += 128) Xs[0][i] = 0.f;
    __syncthreads();
    const int row = tid >> 4, c0 = (tid & 15) * 4;
    const size_t gstride = (size_t)BATCH * NB;
    float* xst = d_Xst + ((size_t)rowBase + row) * NB + c0;
    const float* vsrc = d_V + ((size_t)rowBase + row) * NB + c0;

    float4 xcur = make_float4(0.f, 0.f, 0.f, 0.f);          // X_0
    float4 vnext = *(const float4*)(vsrc);                  // V_0

    for (int j = 0; j < NCH; ++j) {
        *(float4*)(xst + (size_t)j * gstride) = xcur;       // store X_j
        if (j == NCH - 1) break;
        const float4 vcur = vnext;
        if (j < NCH - 2)
            vnext = *(const float4*)(vsrc + (size_t)(j + 1) * gstride);
        const float* xrow = Xs[j & 1] + row * 64;
        float a0 = vcur.x, a1 = vcur.y, a2 = vcur.z, a3 = vcur.w;
        #pragma unroll
        for (int n = 0; n < 64; ++n) {
            float xv = xrow[n];
            float4 m = *(const float4*)(MsT + n * 64 + c0);
            a0 += xv * m.x; a1 += xv * m.y; a2 += xv * m.z; a3 += xv * m.w;
        }
        xcur = make_float4(a0, a1, a2, a3);
        *(float4*)(Xs[(j + 1) & 1] + row * 64 + c0) = xcur;
        __syncthreads();
    }
}

// ---------------- B: Y = [X|U] * PbT  (1024 CTAs x 256, single stage) ------
// u32 layout, pitch 100: AH [128][100], AL, BH [128][100], BL. Total 204800 B.
#define B_AH 0
#define B_AL 12800
#define B_BH 25600
#define B_BL 38400
__global__ void __launch_bounds__(256) ssm_b(const float* __restrict__ u,
                                             float* __restrict__ y) {
    extern __shared__ __align__(16) uint32_t sw[];
    const int tid = threadIdx.x;
    const int j = blockIdx.x >> 4, b0 = (blockIdx.x & 15) << 7;
    const int wid = tid >> 5, lane = tid & 31;
    const int g = lane >> 2, tq = lane & 3;
    const int wm = wid >> 2, wn = wid & 3;          // 2x4 warp grid
    const int RM = wm * 64, CN = wn * 32;

    // fill PbT (128 rows x 96 u32)
    for (int i = tid; i < 12288; i += 256) {
        int r = i / 96, c = i - r * 96;
        sw[B_BH + r * 100 + c] = ((const uint32_t*)d_PbHi)[i];
        sw[B_BL + r * 100 + c] = ((const uint32_t*)d_PbLo)[i];
    }
    // fill A: X part (k u32 0..31)
    for (int i = tid; i < 2048; i += 256) {
        int r = i >> 4, c4 = (i & 15) * 4;
        float4 f = *(const float4*)(d_Xst + ((size_t)j * BATCH + b0 + r) * NB + c4);
        uint32_t h0, l0, h1, l1;
        splitpk(f.x, f.y, h0, l0); splitpk(f.z, f.w, h1, l1);
        int o = r * 100 + (c4 >> 1);
        sw[B_AH + o] = h0; sw[B_AH + o + 1] = h1;
        sw[B_AL + o] = l0; sw[B_AL + o + 1] = l1;
    }
    // fill A: U part (k u32 32..95)
    for (int i = tid; i < 4096; i += 256) {
        int r = i >> 5, q = (i & 31) * 4;
        float4 f = *(const float4*)(u + (size_t)(b0 + r) * L + j * QC + q);
        uint32_t h0, l0, h1, l1;
        splitpk(f.x, f.y, h0, l0); splitpk(f.z, f.w, h1, l1);
        int o = r * 100 + 32 + (q >> 1);
        sw[B_AH + o] = h0; sw[B_AH + o + 1] = h1;
        sw[B_AL + o] = l0; sw[B_AL + o + 1] = l1;
    }
    __syncthreads();

    float acc[4][4][4];
    #pragma unroll
    for (int a = 0; a < 4; ++a)
        #pragma unroll
        for (int bq = 0; bq < 4; ++bq)
            #pragma unroll
            for (int cq = 0; cq < 4; ++cq) acc[a][bq][cq] = 0.f;

    #pragma unroll 4
    for (int it = 0; it < 12; ++it) {
        const int kb = it * 8 + tq;
        uint32_t bh0[4], bh1[4], bl0[4], bl1[4];
        #pragma unroll
        for (int nt = 0; nt < 4; ++nt) {
            int n = CN + nt * 8 + g;
            bh0[nt] = sw[B_BH + n * 100 + kb];
            bh1[nt] = sw[B_BH + n * 100 + kb + 4];
            bl0[nt] = sw[B_BL + n * 100 + kb];
            bl1[nt] = sw[B_BL + n * 100 + kb + 4];
        }
        #pragma unroll
        for (int mt = 0; mt < 4; ++mt) {
            int r0 = RM + mt * 16 + g, r1 = r0 + 8;
            uint32_t ah0 = sw[B_AH + r0 * 100 + kb];
            uint32_t ah1 = sw[B_AH + r1 * 100 + kb];
            uint32_t ah2 = sw[B_AH + r0 * 100 + kb + 4];
            uint32_t ah3 = sw[B_AH + r1 * 100 + kb + 4];
            uint32_t al0 = sw[B_AL + r0 * 100 + kb];
            uint32_t al1 = sw[B_AL + r1 * 100 + kb];
            uint32_t al2 = sw[B_AL + r0 * 100 + kb + 4];
            uint32_t al3 = sw[B_AL + r1 * 100 + kb + 4];
            #pragma unroll
            for (int nt = 0; nt < 4; ++nt) {
                mma16816(acc[mt][nt], ah0, ah1, ah2, ah3, bh0[nt], bh1[nt]);
                mma16816(acc[mt][nt], ah0, ah1, ah2, ah3, bl0[nt], bl1[nt]);
                mma16816(acc[mt][nt], al0, al1, al2, al3, bh0[nt], bh1[nt]);
            }
        }
    }
    #pragma unroll
    for (int mt = 0; mt < 4; ++mt) {
        #pragma unroll
        for (int nt = 0; nt < 4; ++nt) {
            int r0 = RM + mt * 16 + g;
            int col = j * QC + CN + nt * 8 + tq * 2;
            *(float2*)(y + (size_t)(b0 + r0) * L + col)     = make_float2(acc[mt][nt][0], acc[mt][nt][1]);
            *(float2*)(y + (size_t)(b0 + r0 + 8) * L + col) = make_float2(acc[mt][nt][2], acc[mt][nt][3]);
        }
    }
}

extern "C" void kernel_launch(void* const* d_in, const int* in_sizes, int n_in,
                              void* d_out, int out_size) {
    const float* u  = (const float*)d_in[0];
    const float* A  = (const float*)d_in[1];
    const float* B  = (const float*)d_in[2];
    const float* C  = (const float*)d_in[3];
    const float* D  = (const float*)d_in[4];
    const float* ls = (const float*)d_in[5];
    float* y = (float*)d_out;

    const int smA0 = 104448;
    const int smB  = 204800;
    cudaFuncSetAttribute(ssm_a0, cudaFuncAttributeMaxDynamicSharedMemorySize, smA0);
    cudaFuncSetAttribute(ssm_b,  cudaFuncAttributeMaxDynamicSharedMemorySize, smB);

    ssm_gj<<<1, 256>>>(A, B, C, D, ls);
    ssm_mega<<<192, 64>>>();
    ssm_a0<<<1024, 256, smA0>>>(u);
    ssm_a1<<<256, 128>>>();
    ssm_b<<<1024, 256, smB>>>(u, y);
}

// round 14
// speedup vs baseline: 1.2393x; 1.2252x over previous
#include <cuda_runtime.h>
#include <cuda_bf16.h>
#include <cstdint>

#define NB    64          // state size
#define L     8192
#define BATCH 2048
#define QC    128         // chunk length
#define NCH   64          // chunks
#define KB    192         // 64 (X) + 128 (U)

// ---------------- constants built by setup ----------------
__device__ float d_Mf[NB * NB];                               // Ab^128
__device__ __nv_bfloat16 d_WHi[NB * QC],  d_WLo[NB * QC];     // WinT [n][i], pitch 128
__device__ __nv_bfloat16 d_PbHi[QC * KB], d_PbLo[QC * KB];    // PbT  [t][k], pitch 192
__device__ float d_V  [(size_t)NCH * BATCH * NB];             // V[j][b][n]
__device__ float d_Xst[(size_t)NCH * BATCH * NB];             // X[j][b][n]

// fp64 setup workspace
__device__ double d_T[NB * NB], d_R[NB * NB], d_X[NB * NB], d_X2[NB * NB];
__device__ double d_W[NB * NB], d_Ab[NB * NB], d_SA[NB * NB], d_SB[NB * NB];
__device__ double d_Rm[QC + 1][NB], d_Cm[QC][NB], d_Kk[QC];
__device__ double d_Cv[NB], d_Bv[NB], d_Dv, d_sp;
__device__ unsigned g_cnt = 0;
__device__ volatile unsigned g_gen = 0;

// ---------------- helpers ----------------
__device__ __forceinline__ void splitpk(float a, float b, uint32_t& hi, uint32_t& lo) {
    __nv_bfloat16 ha = __float2bfloat16(a), hb = __float2bfloat16(b);
    __nv_bfloat162 h, l;
    h.x = ha; h.y = hb;
    l.x = __float2bfloat16(a - __bfloat162float(ha));
    l.y = __float2bfloat16(b - __bfloat162float(hb));
    hi = *(uint32_t*)&h; lo = *(uint32_t*)&l;
}
__device__ __forceinline__ void mma16816(float* c, uint32_t a0, uint32_t a1,
                                         uint32_t a2, uint32_t a3,
                                         uint32_t b0, uint32_t b1) {
    asm volatile(
        "mma.sync.aligned.m16n8k16.row.col.f32.bf16.bf16.f32 "
        "{%0,%1,%2,%3}, {%4,%5,%6,%7}, {%8,%9}, {%0,%1,%2,%3};"
        : "+f"(c[0]), "+f"(c[1]), "+f"(c[2]), "+f"(c[3])
        : "r"(a0), "r"(a1), "r"(a2), "r"(a3), "r"(b0), "r"(b1));
}
__device__ __forceinline__ double dot64_row(const double* v, const double* S, int t) {
    double a0 = 0, a1 = 0, a2 = 0, a3 = 0;
    #pragma unroll 8
    for (int m = 0; m < 64; m += 4) {
        a0 += v[m]     * S[m * 64 + t];
        a1 += v[m + 1] * S[(m + 1) * 64 + t];
        a2 += v[m + 2] * S[(m + 2) * 64 + t];
        a3 += v[m + 3] * S[(m + 3) * 64 + t];
    }
    return (a0 + a1) + (a2 + a3);
}
__device__ __forceinline__ double dot64_col(const double* S, int t, const double* v) {
    double a0 = 0, a1 = 0, a2 = 0, a3 = 0;
    #pragma unroll 8
    for (int m = 0; m < 64; m += 4) {
        a0 += S[t * 64 + m]     * v[m];
        a1 += S[t * 64 + m + 1] * v[m + 1];
        a2 += S[t * 64 + m + 2] * v[m + 2];
        a3 += S[t * 64 + m + 3] * v[m + 3];
    }
    return (a0 + a1) + (a2 + a3);
}

// ---------------- L0: fp32 Gauss-Jordan seed + fp64 stash ----------------
__global__ void ssm_gj(const float* __restrict__ A, const float* __restrict__ B,
                       const float* __restrict__ C, const float* __restrict__ Dp,
                       const float* __restrict__ ls) {
    __shared__ float G[64 * 128];
    __shared__ float fac[64];
    const int tid = threadIdx.x, nt = 256;
    const double sd = exp((double)ls[0]);
    const float s = (float)sd;
    for (int i = tid; i < 4096; i += nt) {
        int r = i >> 6, c = i & 63;
        double a = (double)A[i];
        d_T[i] = (r == c ? 1.0 : 0.0) - 0.5 * sd * a;
        d_R[i] = (r == c ? 1.0 : 0.0) + 0.5 * sd * a;
    }
    for (int i = tid; i < 8192; i += nt) {
        int r = i >> 7, c = i & 127;
        G[i] = (c < 64) ? ((r == c ? 1.f : 0.f) - 0.5f * s * A[r * 64 + c])
                        : (((c - 64) == r) ? 1.f : 0.f);
    }
    if (tid < 64) { d_Cv[tid] = (double)C[tid]; d_Bv[tid] = (double)B[tid]; }
    if (tid == 0) { d_Dv = (double)Dp[0]; d_sp = sd; }
    __syncthreads();
    for (int p = 0; p < 64; ++p) {
        float pv = 1.f / G[p * 128 + p];
        __syncthreads();
        for (int c = tid; c < 128; c += nt) G[p * 128 + c] *= pv;
        for (int r = tid; r < 64; r += nt) fac[r] = G[r * 128 + p];
        __syncthreads();
        for (int i = tid; i < 8192; i += nt) {
            int r = i >> 7, c = i & 127;
            if (r != p) G[i] -= fac[r] * G[p * 128 + c];
        }
        __syncthreads();
    }
    for (int i = tid; i < 4096; i += nt)
        d_X[i] = (double)G[(i >> 6) * 128 + 64 + (i & 63)];
}

// ---------------- L1: mega setup (192 blocks x 64, grid barrier) ----------
__device__ __forceinline__ void gbar() {
    __syncthreads();
    if (threadIdx.x == 0) {
        __threadfence();
        unsigned g = g_gen;
        if (atomicAdd(&g_cnt, 1u) == 191u) { g_cnt = 0; __threadfence(); g_gen = g + 1; }
        else { while (g_gen == g) __nanosleep(64); __threadfence(); }
    }
    __syncthreads();
}
__global__ void ssm_mega() {
    __shared__ double v[64], red[64];
    const int b = blockIdx.x, t = threadIdx.x;
    if (b < 64) {                                  // W = X*T
        v[t] = d_X[b * 64 + t]; __syncthreads();
        d_W[b * 64 + t] = dot64_row(v, d_T, t);
    }
    gbar();
    if (b < 64) {                                  // X2 = 2X - W*X  (Newton)
        v[t] = d_W[b * 64 + t]; __syncthreads();
        d_X2[b * 64 + t] = 2.0 * d_X[b * 64 + t] - dot64_row(v, d_X, t);
    }
    gbar();
    if (b < 64) {                                  // Ab = X2*R
        v[t] = d_X2[b * 64 + t]; __syncthreads();
        d_Ab[b * 64 + t] = dot64_row(v, d_R, t);
    } else if (b == 64) {                          // Bb; seeds
        v[t] = d_Bv[t]; __syncthreads();
        d_Cm[0][t] = d_sp * dot64_col(d_X2, t, v);
        d_Rm[0][t] = d_Cv[t];
    }
    gbar();
    for (int lev = 0; lev < 7; ++lev) {            // chains + squaring to Ab^128
        int tw = 1 << lev;
        const double* S = (lev == 0) ? d_Ab : ((lev & 1) ? d_SA : d_SB);
        double* Sd = (lev & 1) ? d_SB : d_SA;
        if (b < tw) {
            v[t] = d_Rm[b][t]; __syncthreads();
            d_Rm[b + tw][t] = dot64_row(v, S, t);
        } else if (b < 2 * tw) {
            v[t] = d_Cm[b - tw][t]; __syncthreads();
            d_Cm[b][t] = dot64_col(S, t, v);
        } else if (b < 2 * tw + 64) {
            int r = b - 2 * tw;
            v[t] = S[r * 64 + t]; __syncthreads();
            Sd[r * 64 + t] = dot64_row(v, S, t);
        }
        gbar();
    }
    // M = Ab^128 lives in d_SA
    if (b < QC) {                                  // Kk[b] = C . c_b  (+D at 0)
        red[t] = d_Cv[t] * d_Cm[b][t]; __syncthreads();
        for (int o = 32; o > 0; o >>= 1) { if (t < o) red[t] += red[t + o]; __syncthreads(); }
        if (t == 0) d_Kk[b] = red[0] + ((b == 0) ? d_Dv : 0.0);
    } else if (b == QC) {                          // r_128 = C * M
        v[t] = d_Cv[t]; __syncthreads();
        d_Rm[QC][t] = dot64_row(v, d_SA, t);
    }
    gbar();
    const int gt = b * 64 + t, NT = 192 * 64;      // fills
    for (int i = gt; i < 4096; i += NT) d_Mf[i] = (float)d_SA[i];
    for (int i = gt; i < NB * QC; i += NT) {       // WinT[n][ii] = c_{127-ii}[n]
        int n = i >> 7, ii = i & 127;
        float f = (float)d_Cm[QC - 1 - ii][n];
        __nv_bfloat16 h = __float2bfloat16(f);
        d_WHi[i] = h; d_WLo[i] = __float2bfloat16(f - __bfloat162float(h));
    }
    for (int i = gt; i < QC * KB; i += NT) {       // PbT[t][k]
        int tt = i / KB, k = i % KB;
        double dv;
        if (k < 64) dv = d_Rm[tt + 1][k];
        else { int ii = k - 64; dv = (ii <= tt) ? d_Kk[tt - ii] : 0.0; }
        float f = (float)dv;
        __nv_bfloat16 h = __float2bfloat16(f);
        d_PbHi[i] = h; d_PbLo[i] = __float2bfloat16(f - __bfloat162float(h));
    }
}

// ---------------- A0: V = U * Win  (1024 CTAs x 256, HMMA) -----------------
// smem (u32 units): AH [128][36], AL, BH [64][36], BL  (R9-proven layout)
#define A0_AH 0
#define A0_AL 4608
#define A0_BH 9216
#define A0_BL 11520
__global__ void __launch_bounds__(256) ssm_a0(const float* __restrict__ u) {
    extern __shared__ __align__(16) uint32_t sw[];
    const int tid = threadIdx.x;
    const int j = blockIdx.x >> 4, b0 = (blockIdx.x & 15) << 7;
    const int wid = tid >> 5, lane = tid & 31;
    const int g = lane >> 2, tq = lane & 3;
    const int wm = wid >> 1, wn = wid & 1;          // 4x2 warp grid
    const int RM = wm * 32, CN = wn * 32;

    float acc[2][4][4];
    #pragma unroll
    for (int a = 0; a < 2; ++a)
        #pragma unroll
        for (int bq = 0; bq < 4; ++bq)
            #pragma unroll
            for (int cq = 0; cq < 4; ++cq) acc[a][bq][cq] = 0.f;

    for (int s = 0; s < 2; ++s) {
        for (int i = tid; i < 2048; i += 256) {     // Win slab
            int n = i >> 5, c2 = i & 31;
            sw[A0_BH + n * 36 + c2] = ((const uint32_t*)d_WHi)[n * 64 + s * 32 + c2];
            sw[A0_BL + n * 36 + c2] = ((const uint32_t*)d_WLo)[n * 64 + s * 32 + c2];
        }
        for (int i = tid; i < 2048; i += 256) {     // U slab hi/lo
            int r = i >> 4, c4 = (i & 15) * 4;
            float4 f = *(const float4*)(u + (size_t)(b0 + r) * L + j * QC + s * 64 + c4);
            uint32_t h0, l0, h1, l1;
            splitpk(f.x, f.y, h0, l0); splitpk(f.z, f.w, h1, l1);
            int o = r * 36 + (c4 >> 1);
            sw[A0_AH + o] = h0; sw[A0_AH + o + 1] = h1;
            sw[A0_AL + o] = l0; sw[A0_AL + o + 1] = l1;
        }
        __syncthreads();
        #pragma unroll
        for (int kk = 0; kk < 64; kk += 16) {
            const int kb = (kk >> 1) + tq;
            uint32_t bh0[4], bh1[4], bl0[4], bl1[4];
            #pragma unroll
            for (int nt = 0; nt < 4; ++nt) {
                int n = CN + nt * 8 + g;
                bh0[nt] = sw[A0_BH + n * 36 + kb];
                bh1[nt] = sw[A0_BH + n * 36 + kb + 4];
                bl0[nt] = sw[A0_BL + n * 36 + kb];
                bl1[nt] = sw[A0_BL + n * 36 + kb + 4];
            }
            #pragma unroll
            for (int mt = 0; mt < 2; ++mt) {
                int r0 = RM + mt * 16 + g, r1 = r0 + 8;
                uint32_t ah0 = sw[A0_AH + r0 * 36 + kb];
                uint32_t ah1 = sw[A0_AH + r1 * 36 + kb];
                uint32_t ah2 = sw[A0_AH + r0 * 36 + kb + 4];
                uint32_t ah3 = sw[A0_AH + r1 * 36 + kb + 4];
                uint32_t al0 = sw[A0_AL + r0 * 36 + kb];
                uint32_t al1 = sw[A0_AL + r1 * 36 + kb];
                uint32_t al2 = sw[A0_AL + r0 * 36 + kb + 4];
                uint32_t al3 = sw[A0_AL + r1 * 36 + kb + 4];
                #pragma unroll
                for (int nt = 0; nt < 4; ++nt) {
                    mma16816(acc[mt][nt], ah0, ah1, ah2, ah3, bh0[nt], bh1[nt]);
                    mma16816(acc[mt][nt], ah0, ah1, ah2, ah3, bl0[nt], bl1[nt]);
                    mma16816(acc[mt][nt], al0, al1, al2, al3, bh0[nt], bh1[nt]);
                }
            }
        }
        __syncthreads();
    }
    #pragma unroll
    for (int mt = 0; mt < 2; ++mt) {
        #pragma unroll
        for (int nt = 0; nt < 4; ++nt) {
            int r0 = RM + mt * 16 + g, c = CN + nt * 8 + tq * 2;
            float* vp = d_V + ((size_t)j * BATCH + b0) * NB;
            *(float2*)(vp + (size_t)r0 * NB + c)       = make_float2(acc[mt][nt][0], acc[mt][nt][1]);
            *(float2*)(vp + (size_t)(r0 + 8) * NB + c) = make_float2(acc[mt][nt][2], acc[mt][nt][3]);
        }
    }
}

// ---------------- A1: warp-local sequential scan (256 CTAs x 128) ----------
// Warp w owns rows {2w, 2w+1}; lane reads only its own row's X and writes 4
// entries -> inter-step hazard is warp-internal: __syncwarp, no block barrier.
__global__ void __launch_bounds__(128) ssm_a1() {
    __shared__ float MsT[4096];      // [n][c] = Mf[c][n]
    __shared__ float Xs[512];        // [row][n], 8 rows
    const int tid = threadIdx.x;
    const int rowBase = blockIdx.x * 8;
    for (int i = tid; i < 4096; i += 128) MsT[i] = d_Mf[(i & 63) * 64 + (i >> 6)];
    for (int i = tid; i < 512; i += 128) Xs[i] = 0.f;
    __syncthreads();

    const int lane = tid & 31, w = tid >> 5;
    const int row = 2 * w + (lane >> 4);       // warp-local row pair
    const int c0 = (lane & 15) * 4;
    float* xrow = Xs + row * 64;
    const size_t gstride = (size_t)BATCH * NB;
    float* xst = d_Xst + ((size_t)rowBase + row) * NB + c0;
    const float* vsrc = d_V + ((size_t)rowBase + row) * NB + c0;

    float4 xcur = make_float4(0.f, 0.f, 0.f, 0.f);          // X_0
    float4 vnext = *(const float4*)(vsrc);                  // V_0

    for (int j = 0; j < NCH; ++j) {
        *(float4*)(xst + (size_t)j * gstride) = xcur;       // store X_j (regs)
        if (j == NCH - 1) break;
        const float4 vcur = vnext;
        if (j < NCH - 2)
            vnext = *(const float4*)(vsrc + (size_t)(j + 1) * gstride);
        float a0 = vcur.x, a1 = vcur.y, a2 = vcur.z, a3 = vcur.w;
        #pragma unroll
        for (int n = 0; n < 64; ++n) {
            float xv = xrow[n];
            float4 m = *(const float4*)(MsT + n * 64 + c0);
            a0 += xv * m.x; a1 += xv * m.y; a2 += xv * m.z; a3 += xv * m.w;
        }
        xcur = make_float4(a0, a1, a2, a3);
        __syncwarp();                                       // all reads done
        *(float4*)(xrow + c0) = xcur;
        __syncwarp();                                       // writes visible
    }
}

// ---------------- B: Y = [X|U] * PbT  (1024 CTAs x 256, 3-slab, R9) --------
#define B_AH 0
#define B_AL 4608
#define B_BH 9216
#define B_BL 13824
__global__ void __launch_bounds__(256) ssm_b(const float* __restrict__ u,
                                             float* __restrict__ y) {
    extern __shared__ __align__(16) uint32_t sw[];
    const int tid = threadIdx.x;
    const int j = blockIdx.x >> 4, b0 = (blockIdx.x & 15) << 7;
    const int wid = tid >> 5, lane = tid & 31;
    const int g = lane >> 2, tq = lane & 3;
    const int wm = wid >> 2, wn = wid & 3;          // 2x4 warp grid
    const int RM = wm * 64, CN = wn * 32;

    float acc[4][4][4];
    #pragma unroll
    for (int a = 0; a < 4; ++a)
        #pragma unroll
        for (int bq = 0; bq < 4; ++bq)
            #pragma unroll
            for (int cq = 0; cq < 4; ++cq) acc[a][bq][cq] = 0.f;

    for (int s = 0; s < 3; ++s) {
        for (int i = tid; i < 4096; i += 256) {     // PbT slab
            int t2 = i >> 5, c2 = i & 31;
            sw[B_BH + t2 * 36 + c2] = ((const uint32_t*)d_PbHi)[t2 * 96 + s * 32 + c2];
            sw[B_BL + t2 * 36 + c2] = ((const uint32_t*)d_PbLo)[t2 * 96 + s * 32 + c2];
        }
        for (int i = tid; i < 2048; i += 256) {     // A slab (s=0: X, else U)
            int r = i >> 4, c4 = (i & 15) * 4;
            float4 f;
            if (s == 0)
                f = *(const float4*)(d_Xst + ((size_t)j * BATCH + b0 + r) * NB + c4);
            else
                f = *(const float4*)(u + (size_t)(b0 + r) * L + j * QC + (s - 1) * 64 + c4);
            uint32_t h0, l0, h1, l1;
            splitpk(f.x, f.y, h0, l0); splitpk(f.z, f.w, h1, l1);
            int o = r * 36 + (c4 >> 1);
            sw[B_AH + o] = h0; sw[B_AH + o + 1] = h1;
            sw[B_AL + o] = l0; sw[B_AL + o + 1] = l1;
        }
        __syncthreads();
        #pragma unroll
        for (int kk = 0; kk < 64; kk += 16) {
            const int kb = (kk >> 1) + tq;
            uint32_t bh0[4], bh1[4], bl0[4], bl1[4];
            #pragma unroll
            for (int nt = 0; nt < 4; ++nt) {
                int n = CN + nt * 8 + g;
                bh0[nt] = sw[B_BH + n * 36 + kb];
                bh1[nt] = sw[B_BH + n * 36 + kb + 4];
                bl0[nt] = sw[B_BL + n * 36 + kb];
                bl1[nt] = sw[B_BL + n * 36 + kb + 4];
            }
            #pragma unroll
            for (int mt = 0; mt < 4; ++mt) {
                int r0 = RM + mt * 16 + g, r1 = r0 + 8;
                uint32_t ah0 = sw[B_AH + r0 * 36 + kb];
                uint32_t ah1 = sw[B_AH + r1 * 36 + kb];
                uint32_t ah2 = sw[B_AH + r0 * 36 + kb + 4];
                uint32_t ah3 = sw[B_AH + r1 * 36 + kb + 4];
                uint32_t al0 = sw[B_AL + r0 * 36 + kb];
                uint32_t al1 = sw[B_AL + r1 * 36 + kb];
                uint32_t al2 = sw[B_AL + r0 * 36 + kb + 4];
                uint32_t al3 = sw[B_AL + r1 * 36 + kb + 4];
                #pragma unroll
                for (int nt = 0; nt < 4; ++nt) {
                    mma16816(acc[mt][nt], ah0, ah1, ah2, ah3, bh0[nt], bh1[nt]);
                    mma16816(acc[mt][nt], ah0, ah1, ah2, ah3, bl0[nt], bl1[nt]);
                    mma16816(acc[mt][nt], al0, al1, al2, al3, bh0[nt], bh1[nt]);
                }
            }
        }
        __syncthreads();
    }
    #pragma unroll
    for (int mt = 0; mt < 4; ++mt) {
        #pragma unroll
        for (int nt = 0; nt < 4; ++nt) {
            int r0 = RM + mt * 16 + g;
            int col = j * QC + CN + nt * 8 + tq * 2;
            *(float2*)(y + (size_t)(b0 + r0) * L + col)     = make_float2(acc[mt][nt][0], acc[mt][nt][1]);
            *(float2*)(y + (size_t)(b0 + r0 + 8) * L + col) = make_float2(acc[mt][nt][2], acc[mt][nt][3]);
        }
    }
}

extern "C" void kernel_launch(void* const* d_in, const int* in_sizes, int n_in,
                              void* d_out, int out_size) {
    const float* u  = (const float*)d_in[0];
    const float* A  = (const float*)d_in[1];
    const float* B  = (const float*)d_in[2];
    const float* C  = (const float*)d_in[3];
    const float* D  = (const float*)d_in[4];
    const float* ls = (const float*)d_in[5];
    float* y = (float*)d_out;

    const int smA0 = 13824 * 4;   // 55296 B  (2-3 CTAs/SM)
    const int smB  = 18432 * 4;   // 73728 B  (3 CTAs/SM)
    cudaFuncSetAttribute(ssm_a0, cudaFuncAttributeMaxDynamicSharedMemorySize, smA0);
    cudaFuncSetAttribute(ssm_b,  cudaFuncAttributeMaxDynamicSharedMemorySize, smB);

    ssm_gj<<<1, 256>>>(A, B, C, D, ls);
    ssm_mega<<<192, 64>>>();
    ssm_a0<<<1024, 256, smA0>>>(u);
    ssm_a1<<<256, 128>>>();
    ssm_b<<<1024, 256, smB>>>(u, y);
}

// round 15
// speedup vs baseline: 1.3505x; 1.0897x over previous
#include <cuda_runtime.h>
#include <cuda_bf16.h>
#include <cstdint>

#define NB    64          // state size
#define L     8192
#define BATCH 2048
#define QC    128         // chunk length
#define NCH   64          // chunks
#define KB    192         // 64 (X) + 128 (U)

// ---------------- constants built by setup ----------------
__device__ float d_Mf[NB * NB];                               // Ab^128
__device__ __nv_bfloat16 d_WHi[NB * QC],  d_WLo[NB * QC];     // WinT [n][i], pitch 128
__device__ __nv_bfloat16 d_PbHi[QC * KB], d_PbLo[QC * KB];    // PbT  [t][k], pitch 192
__device__ float d_V  [(size_t)NCH * BATCH * NB];             // V[j][b][n]
__device__ float d_Xst[(size_t)NCH * BATCH * NB];             // X[j][b][n]

// fp64 setup workspace
__device__ double d_T[NB * NB], d_R[NB * NB], d_X[NB * NB], d_X2[NB * NB];
__device__ double d_W[NB * NB], d_Ab[NB * NB], d_SA[NB * NB], d_SB[NB * NB];
__device__ double d_Rm[QC + 1][NB], d_Cm[QC][NB], d_Kk[QC];
__device__ double d_Cv[NB], d_Bv[NB], d_Dv, d_sp;
__device__ unsigned g_cnt = 0;
__device__ volatile unsigned g_gen = 0;

// ---------------- helpers ----------------
__device__ __forceinline__ uint32_t s2u(const void* p) {
    uint32_t a;
    asm("{ .reg .u64 t; cvta.to.shared.u64 t, %1; cvt.u32.u64 %0, t; }" : "=r"(a) : "l"(p));
    return a;
}
__device__ __forceinline__ void splitpk(float a, float b, uint32_t& hi, uint32_t& lo) {
    __nv_bfloat16 ha = __float2bfloat16(a), hb = __float2bfloat16(b);
    __nv_bfloat162 h, l;
    h.x = ha; h.y = hb;
    l.x = __float2bfloat16(a - __bfloat162float(ha));
    l.y = __float2bfloat16(b - __bfloat162float(hb));
    hi = *(uint32_t*)&h; lo = *(uint32_t*)&l;
}
__device__ __forceinline__ void mma16816(float* c, uint32_t a0, uint32_t a1,
                                         uint32_t a2, uint32_t a3,
                                         uint32_t b0, uint32_t b1) {
    asm volatile(
        "mma.sync.aligned.m16n8k16.row.col.f32.bf16.bf16.f32 "
        "{%0,%1,%2,%3}, {%4,%5,%6,%7}, {%8,%9}, {%0,%1,%2,%3};"
        : "+f"(c[0]), "+f"(c[1]), "+f"(c[2]), "+f"(c[3])
        : "r"(a0), "r"(a1), "r"(a2), "r"(a3), "r"(b0), "r"(b1));
}
__device__ __forceinline__ void ldsm4(uint32_t& d0, uint32_t& d1, uint32_t& d2,
                                      uint32_t& d3, uint32_t saddr) {
    asm volatile("ldmatrix.sync.aligned.m8n8.x4.shared.b16 {%0,%1,%2,%3}, [%4];"
                 : "=r"(d0), "=r"(d1), "=r"(d2), "=r"(d3) : "r"(saddr));
}
__device__ __forceinline__ double dot64_row(const double* v, const double* S, int t) {
    double a0 = 0, a1 = 0, a2 = 0, a3 = 0;
    #pragma unroll 8
    for (int m = 0; m < 64; m += 4) {
        a0 += v[m]     * S[m * 64 + t];
        a1 += v[m + 1] * S[(m + 1) * 64 + t];
        a2 += v[m + 2] * S[(m + 2) * 64 + t];
        a3 += v[m + 3] * S[(m + 3) * 64 + t];
    }
    return (a0 + a1) + (a2 + a3);
}
__device__ __forceinline__ double dot64_col(const double* S, int t, const double* v) {
    double a0 = 0, a1 = 0, a2 = 0, a3 = 0;
    #pragma unroll 8
    for (int m = 0; m < 64; m += 4) {
        a0 += S[t * 64 + m]     * v[m];
        a1 += S[t * 64 + m + 1] * v[m + 1];
        a2 += S[t * 64 + m + 2] * v[m + 2];
        a3 += S[t * 64 + m + 3] * v[m + 3];
    }
    return (a0 + a1) + (a2 + a3);
}

// ---------------- L0: fp32 Gauss-Jordan seed + fp64 stash ----------------
__global__ void ssm_gj(const float* __restrict__ A, const float* __restrict__ B,
                       const float* __restrict__ C, const float* __restrict__ Dp,
                       const float* __restrict__ ls) {
    __shared__ float G[64 * 128];
    __shared__ float fac[64];
    const int tid = threadIdx.x, nt = 256;
    const double sd = exp((double)ls[0]);
    const float s = (float)sd;
    for (int i = tid; i < 4096; i += nt) {
        int r = i >> 6, c = i & 63;
        double a = (double)A[i];
        d_T[i] = (r == c ? 1.0 : 0.0) - 0.5 * sd * a;
        d_R[i] = (r == c ? 1.0 : 0.0) + 0.5 * sd * a;
    }
    for (int i = tid; i < 8192; i += nt) {
        int r = i >> 7, c = i & 127;
        G[i] = (c < 64) ? ((r == c ? 1.f : 0.f) - 0.5f * s * A[r * 64 + c])
                        : (((c - 64) == r) ? 1.f : 0.f);
    }
    if (tid < 64) { d_Cv[tid] = (double)C[tid]; d_Bv[tid] = (double)B[tid]; }
    if (tid == 0) { d_Dv = (double)Dp[0]; d_sp = sd; }
    __syncthreads();
    for (int p = 0; p < 64; ++p) {
        float pv = 1.f / G[p * 128 + p];
        __syncthreads();
        for (int c = tid; c < 128; c += nt) G[p * 128 + c] *= pv;
        for (int r = tid; r < 64; r += nt) fac[r] = G[r * 128 + p];
        __syncthreads();
        for (int i = tid; i < 8192; i += nt) {
            int r = i >> 7, c = i & 127;
            if (r != p) G[i] -= fac[r] * G[p * 128 + c];
        }
        __syncthreads();
    }
    for (int i = tid; i < 4096; i += nt)
        d_X[i] = (double)G[(i >> 6) * 128 + 64 + (i & 63)];
}

// ---------------- L1: mega setup (192 blocks x 64, grid barrier) ----------
__device__ __forceinline__ void gbar() {
    __syncthreads();
    if (threadIdx.x == 0) {
        __threadfence();
        unsigned g = g_gen;
        if (atomicAdd(&g_cnt, 1u) == 191u) { g_cnt = 0; __threadfence(); g_gen = g + 1; }
        else { while (g_gen == g) __nanosleep(64); __threadfence(); }
    }
    __syncthreads();
}
__global__ void ssm_mega() {
    __shared__ double v[64], red[64];
    const int b = blockIdx.x, t = threadIdx.x;
    if (b < 64) {                                  // W = X*T
        v[t] = d_X[b * 64 + t]; __syncthreads();
        d_W[b * 64 + t] = dot64_row(v, d_T, t);
    }
    gbar();
    if (b < 64) {                                  // X2 = 2X - W*X  (Newton)
        v[t] = d_W[b * 64 + t]; __syncthreads();
        d_X2[b * 64 + t] = 2.0 * d_X[b * 64 + t] - dot64_row(v, d_X, t);
    }
    gbar();
    if (b < 64) {                                  // Ab = X2*R
        v[t] = d_X2[b * 64 + t]; __syncthreads();
        d_Ab[b * 64 + t] = dot64_row(v, d_R, t);
    } else if (b == 64) {                          // Bb; seeds
        v[t] = d_Bv[t]; __syncthreads();
        d_Cm[0][t] = d_sp * dot64_col(d_X2, t, v);
        d_Rm[0][t] = d_Cv[t];
    }
    gbar();
    for (int lev = 0; lev < 7; ++lev) {            // chains + squaring to Ab^128
        int tw = 1 << lev;
        const double* S = (lev == 0) ? d_Ab : ((lev & 1) ? d_SA : d_SB);
        double* Sd = (lev & 1) ? d_SB : d_SA;
        if (b < tw) {
            v[t] = d_Rm[b][t]; __syncthreads();
            d_Rm[b + tw][t] = dot64_row(v, S, t);
        } else if (b < 2 * tw) {
            v[t] = d_Cm[b - tw][t]; __syncthreads();
            d_Cm[b][t] = dot64_col(S, t, v);
        } else if (b < 2 * tw + 64) {
            int r = b - 2 * tw;
            v[t] = S[r * 64 + t]; __syncthreads();
            Sd[r * 64 + t] = dot64_row(v, S, t);
        }
        gbar();
    }
    // M = Ab^128 lives in d_SA
    if (b < QC) {                                  // Kk[b] = C . c_b  (+D at 0)
        red[t] = d_Cv[t] * d_Cm[b][t]; __syncthreads();
        for (int o = 32; o > 0; o >>= 1) { if (t < o) red[t] += red[t + o]; __syncthreads(); }
        if (t == 0) d_Kk[b] = red[0] + ((b == 0) ? d_Dv : 0.0);
    } else if (b == QC) {                          // r_128 = C * M
        v[t] = d_Cv[t]; __syncthreads();
        d_Rm[QC][t] = dot64_row(v, d_SA, t);
    }
    gbar();
    const int gt = b * 64 + t, NT = 192 * 64;      // fills
    for (int i = gt; i < 4096; i += NT) d_Mf[i] = (float)d_SA[i];
    for (int i = gt; i < NB * QC; i += NT) {       // WinT[n][ii] = c_{127-ii}[n]
        int n = i >> 7, ii = i & 127;
        float f = (float)d_Cm[QC - 1 - ii][n];
        __nv_bfloat16 h = __float2bfloat16(f);
        d_WHi[i] = h; d_WLo[i] = __float2bfloat16(f - __bfloat162float(h));
    }
    for (int i = gt; i < QC * KB; i += NT) {       // PbT[t][k]
        int tt = i / KB, k = i % KB;
        double dv;
        if (k < 64) dv = d_Rm[tt + 1][k];
        else { int ii = k - 64; dv = (ii <= tt) ? d_Kk[tt - ii] : 0.0; }
        float f = (float)dv;
        __nv_bfloat16 h = __float2bfloat16(f);
        d_PbHi[i] = h; d_PbLo[i] = __float2bfloat16(f - __bfloat162float(h));
    }
}

// ---------------- A0: V = U * Win  (1024 CTAs x 256, ldmatrix) -------------
// smem (u32 units): AH [128][36], AL, BH [64][36], BL
#define A0_AH 0
#define A0_AL 4608
#define A0_BH 9216
#define A0_BL 11520
__global__ void __launch_bounds__(256) ssm_a0(const float* __restrict__ u) {
    extern __shared__ __align__(16) uint32_t sw[];
    const uint32_t sb = s2u(sw);
    const int tid = threadIdx.x;
    const int j = blockIdx.x >> 4, b0 = (blockIdx.x & 15) << 7;
    const int wid = tid >> 5, lane = tid & 31;
    const int g = lane >> 2, tq = lane & 3;
    const int wm = wid >> 1, wn = wid & 1;          // 4x2 warp grid
    const int RM = wm * 32, CN = wn * 32;

    // ldmatrix lane-offset pieces
    const int alr = lane & 15, ahf = lane >> 4;                 // A map
    const int bq = lane >> 3;
    const int brow = (lane & 7) + ((bq >> 1) << 3);             // B map within pair
    const int boff = (bq & 1) * 16;

    float acc[2][4][4];
    #pragma unroll
    for (int a = 0; a < 2; ++a)
        #pragma unroll
        for (int q2 = 0; q2 < 4; ++q2)
            #pragma unroll
            for (int cq = 0; cq < 4; ++cq) acc[a][q2][cq] = 0.f;

    for (int s = 0; s < 2; ++s) {
        for (int i = tid; i < 2048; i += 256) {     // Win slab
            int n = i >> 5, c2 = i & 31;
            sw[A0_BH + n * 36 + c2] = ((const uint32_t*)d_WHi)[n * 64 + s * 32 + c2];
            sw[A0_BL + n * 36 + c2] = ((const uint32_t*)d_WLo)[n * 64 + s * 32 + c2];
        }
        for (int i = tid; i < 2048; i += 256) {     // U slab hi/lo
            int r = i >> 4, c4 = (i & 15) * 4;
            float4 f = *(const float4*)(u + (size_t)(b0 + r) * L + j * QC + s * 64 + c4);
            uint32_t h0, l0, h1, l1;
            splitpk(f.x, f.y, h0, l0); splitpk(f.z, f.w, h1, l1);
            int o = r * 36 + (c4 >> 1);
            sw[A0_AH + o] = h0; sw[A0_AH + o + 1] = h1;
            sw[A0_AL + o] = l0; sw[A0_AL + o + 1] = l1;
        }
        __syncthreads();
        #pragma unroll
        for (int kt = 0; kt < 4; ++kt) {
            uint32_t bh[2][4], bl[2][4];
            #pragma unroll
            for (int p = 0; p < 2; ++p) {
                uint32_t bo = (uint32_t)(CN + p * 16 + brow) * 144 + kt * 32 + boff;
                ldsm4(bh[p][0], bh[p][1], bh[p][2], bh[p][3], sb + A0_BH * 4 + bo);
                ldsm4(bl[p][0], bl[p][1], bl[p][2], bl[p][3], sb + A0_BL * 4 + bo);
            }
            #pragma unroll
            for (int mt = 0; mt < 2; ++mt) {
                uint32_t ao = (uint32_t)(RM + mt * 16 + alr) * 144 + kt * 32 + ahf * 16;
                uint32_t ah0, ah1, ah2, ah3, al0, al1, al2, al3;
                ldsm4(ah0, ah1, ah2, ah3, sb + A0_AH * 4 + ao);
                ldsm4(al0, al1, al2, al3, sb + A0_AL * 4 + ao);
                #pragma unroll
                for (int p = 0; p < 2; ++p)
                    #pragma unroll
                    for (int h = 0; h < 2; ++h) {
                        float* c = acc[mt][p * 2 + h];
                        mma16816(c, ah0, ah1, ah2, ah3, bh[p][2 * h], bh[p][2 * h + 1]);
                        mma16816(c, ah0, ah1, ah2, ah3, bl[p][2 * h], bl[p][2 * h + 1]);
                        mma16816(c, al0, al1, al2, al3, bh[p][2 * h], bh[p][2 * h + 1]);
                    }
            }
        }
        __syncthreads();
    }
    #pragma unroll
    for (int mt = 0; mt < 2; ++mt)
        #pragma unroll
        for (int q2 = 0; q2 < 4; ++q2) {
            int r0 = RM + mt * 16 + g, c = CN + q2 * 8 + tq * 2;
            float* vp = d_V + ((size_t)j * BATCH + b0) * NB;
            *(float2*)(vp + (size_t)r0 * NB + c)       = make_float2(acc[mt][q2][0], acc[mt][q2][1]);
            *(float2*)(vp + (size_t)(r0 + 8) * NB + c) = make_float2(acc[mt][q2][2], acc[mt][q2][3]);
        }
}

// ---------------- A1: MMA sequential scan (128 CTAs x 128) -----------------
// CTA owns 16 batch rows. Warp w owns output cols [16w,16w+16).
// M kept in registers as B-fragments (3-split hi/lo) loaded ONCE.
// X: fp32 accumulator fragments; split-bf16 double-buffered in smem per step.
__global__ void __launch_bounds__(128) ssm_a1() {
    __shared__ uint32_t Ms[2][64 * 36];       // M hi/lo, pitch 36 u32
    __shared__ uint32_t Xb[2][2][16 * 36];    // [buf][hi/lo][row][36]
    const int tid = threadIdx.x, lane = tid & 31, w = tid >> 5;
    const int rowBase = blockIdx.x * 16;
    const uint32_t msb0 = s2u(&Ms[0][0]), msb1 = s2u(&Ms[1][0]);

    // stage M split (B[c][n] = Mf[c][n] row-major)
    for (int i = tid; i < 64 * 32; i += 128) {
        int c = i >> 5, n2 = i & 31;
        uint32_t h, l;
        splitpk(d_Mf[c * 64 + n2 * 2], d_Mf[c * 64 + n2 * 2 + 1], h, l);
        Ms[0][c * 36 + n2] = h; Ms[1][c * 36 + n2] = l;
    }
    for (int i = tid; i < 16 * 36; i += 128) { Xb[0][0][i] = 0; Xb[0][1][i] = 0; }
    __syncthreads();

    // M b-frags: warp w covers cols 16w..16w+15 (one x4 per kt per hi/lo)
    const int bq = lane >> 3;
    const int brow = (lane & 7) + ((bq >> 1) << 3);
    const int boff = (bq & 1) * 16;
    uint32_t mb[2][4][4];
    #pragma unroll
    for (int kt = 0; kt < 4; ++kt) {
        uint32_t bo = (uint32_t)(w * 16 + brow) * 144 + kt * 32 + boff;
        ldsm4(mb[0][kt][0], mb[0][kt][1], mb[0][kt][2], mb[0][kt][3], msb0 + bo);
        ldsm4(mb[1][kt][0], mb[1][kt][1], mb[1][kt][2], mb[1][kt][3], msb1 + bo);
    }

    const int g = lane >> 2, tq = lane & 3;
    const int alr = lane & 15, ahf = lane >> 4;
    const size_t gst = (size_t)BATCH * NB;
    // fragment gmem pointers (nt=0; nt=1 at +8)
    float* x0 = d_Xst + ((size_t)rowBase + g) * NB + w * 16 + tq * 2;
    float* x1 = d_Xst + ((size_t)rowBase + g + 8) * NB + w * 16 + tq * 2;
    const float* v0 = d_V + ((size_t)rowBase + g) * NB + w * 16 + tq * 2;
    const float* v1 = d_V + ((size_t)rowBase + g + 8) * NB + w * 16 + tq * 2;

    float acc[2][4];                                   // X_j fragment (fp32)
    #pragma unroll
    for (int q2 = 0; q2 < 2; ++q2)
        #pragma unroll
        for (int cq = 0; cq < 4; ++cq) acc[q2][cq] = 0.f;

    float2 vp00 = *(const float2*)(v0), vp01 = *(const float2*)(v0 + 8);
    float2 vp10 = *(const float2*)(v1), vp11 = *(const float2*)(v1 + 8);

    for (int j = 0; j < NCH; ++j) {
        // store X_j (fp32, from regs)
        *(float2*)(x0 + (size_t)j * gst)     = make_float2(acc[0][0], acc[0][1]);
        *(float2*)(x0 + (size_t)j * gst + 8) = make_float2(acc[1][0], acc[1][1]);
        *(float2*)(x1 + (size_t)j * gst)     = make_float2(acc[0][2], acc[0][3]);
        *(float2*)(x1 + (size_t)j * gst + 8) = make_float2(acc[1][2], acc[1][3]);
        if (j == NCH - 1) break;

        // init next acc with V_j fragments (prefetched); issue prefetch j+1
        acc[0][0] = vp00.x; acc[0][1] = vp00.y; acc[1][0] = vp01.x; acc[1][1] = vp01.y;
        acc[0][2] = vp10.x; acc[0][3] = vp10.y; acc[1][2] = vp11.x; acc[1][3] = vp11.y;
        if (j + 1 < NCH - 1) {
            vp00 = *(const float2*)(v0 + (size_t)(j + 1) * gst);
            vp01 = *(const float2*)(v0 + (size_t)(j + 1) * gst + 8);
            vp10 = *(const float2*)(v1 + (size_t)(j + 1) * gst);
            vp11 = *(const float2*)(v1 + (size_t)(j + 1) * gst + 8);
        }

        // X_{j+1} = X_j * M^T + V_j  (3-split)
        const uint32_t xh = s2u(&Xb[j & 1][0][0]), xl = s2u(&Xb[j & 1][1][0]);
        #pragma unroll
        for (int kt = 0; kt < 4; ++kt) {
            uint32_t ao = (uint32_t)alr * 144 + kt * 32 + ahf * 16;
            uint32_t ah0, ah1, ah2, ah3, al0, al1, al2, al3;
            ldsm4(ah0, ah1, ah2, ah3, xh + ao);
            ldsm4(al0, al1, al2, al3, xl + ao);
            #pragma unroll
            for (int h = 0; h < 2; ++h) {
                float* c = acc[h];
                mma16816(c, ah0, ah1, ah2, ah3, mb[0][kt][2 * h], mb[0][kt][2 * h + 1]);
                mma16816(c, ah0, ah1, ah2, ah3, mb[1][kt][2 * h], mb[1][kt][2 * h + 1]);
                mma16816(c, al0, al1, al2, al3, mb[0][kt][2 * h], mb[0][kt][2 * h + 1]);
            }
        }
        // split to bf16 and store into next buffer
        uint32_t* nh = &Xb[(j + 1) & 1][0][0];
        uint32_t* nl = &Xb[(j + 1) & 1][1][0];
        #pragma unroll
        for (int h = 0; h < 2; ++h) {
            uint32_t hi, lo;
            int col = w * 8 + h * 4 + tq;               // u32 col
            splitpk(acc[h][0], acc[h][1], hi, lo);
            nh[g * 36 + col] = hi; nl[g * 36 + col] = lo;
            splitpk(acc[h][2], acc[h][3], hi, lo);
            nh[(g + 8) * 36 + col] = hi; nl[(g + 8) * 36 + col] = lo;
        }
        __syncthreads();
    }
}

// ---------------- B: Y = [X|U] * PbT  (1024 CTAs x 256, ldmatrix) ----------
#define B_AH 0
#define B_AL 4608
#define B_BH 9216
#define B_BL 13824
__global__ void __launch_bounds__(256) ssm_b(const float* __restrict__ u,
                                             float* __restrict__ y) {
    extern __shared__ __align__(16) uint32_t sw[];
    const uint32_t sb = s2u(sw);
    const int tid = threadIdx.x;
    const int j = blockIdx.x >> 4, b0 = (blockIdx.x & 15) << 7;
    const int wid = tid >> 5, lane = tid & 31;
    const int g = lane >> 2, tq = lane & 3;
    const int wm = wid >> 2, wn = wid & 3;          // 2x4 warp grid
    const int RM = wm * 64, CN = wn * 32;

    const int alr = lane & 15, ahf = lane >> 4;
    const int bq = lane >> 3;
    const int brow = (lane & 7) + ((bq >> 1) << 3);
    const int boff = (bq & 1) * 16;

    float acc[4][4][4];
    #pragma unroll
    for (int a = 0; a < 4; ++a)
        #pragma unroll
        for (int q2 = 0; q2 < 4; ++q2)
            #pragma unroll
            for (int cq = 0; cq < 4; ++cq) acc[a][q2][cq] = 0.f;

    for (int s = 0; s < 3; ++s) {
        for (int i = tid; i < 4096; i += 256) {     // PbT slab
            int t2 = i >> 5, c2 = i & 31;
            sw[B_BH + t2 * 36 + c2] = ((const uint32_t*)d_PbHi)[t2 * 96 + s * 32 + c2];
            sw[B_BL + t2 * 36 + c2] = ((const uint32_t*)d_PbLo)[t2 * 96 + s * 32 + c2];
        }
        for (int i = tid; i < 2048; i += 256) {     // A slab (s=0: X, else U)
            int r = i >> 4, c4 = (i & 15) * 4;
            float4 f;
            if (s == 0)
                f = *(const float4*)(d_Xst + ((size_t)j * BATCH + b0 + r) * NB + c4);
            else
                f = *(const float4*)(u + (size_t)(b0 + r) * L + j * QC + (s - 1) * 64 + c4);
            uint32_t h0, l0, h1, l1;
            splitpk(f.x, f.y, h0, l0); splitpk(f.z, f.w, h1, l1);
            int o = r * 36 + (c4 >> 1);
            sw[B_AH + o] = h0; sw[B_AH + o + 1] = h1;
            sw[B_AL + o] = l0; sw[B_AL + o + 1] = l1;
        }
        __syncthreads();
        #pragma unroll
        for (int kt = 0; kt < 4; ++kt) {
            uint32_t bh[2][4], bl[2][4];
            #pragma unroll
            for (int p = 0; p < 2; ++p) {
                uint32_t bo = (uint32_t)(CN + p * 16 + brow) * 144 + kt * 32 + boff;
                ldsm4(bh[p][0], bh[p][1], bh[p][2], bh[p][3], sb + B_BH * 4 + bo);
                ldsm4(bl[p][0], bl[p][1], bl[p][2], bl[p][3], sb + B_BL * 4 + bo);
            }
            #pragma unroll
            for (int mt = 0; mt < 4; ++mt) {
                uint32_t ao = (uint32_t)(RM + mt * 16 + alr) * 144 + kt * 32 + ahf * 16;
                uint32_t ah0, ah1, ah2, ah3, al0, al1, al2, al3;
                ldsm4(ah0, ah1, ah2, ah3, sb + B_AH * 4 + ao);
                ldsm4(al0, al1, al2, al3, sb + B_AL * 4 + ao);
                #pragma unroll
                for (int p = 0; p < 2; ++p)
                    #pragma unroll
                    for (int h = 0; h < 2; ++h) {
                        float* c = acc[mt][p * 2 + h];
                        mma16816(c, ah0, ah1, ah2, ah3, bh[p][2 * h], bh[p][2 * h + 1]);
                        mma16816(c, ah0, ah1, ah2, ah3, bl[p][2 * h], bl[p][2 * h + 1]);
                        mma16816(c, al0, al1, al2, al3, bh[p][2 * h], bh[p][2 * h + 1]);
                    }
            }
        }
        __syncthreads();
    }
    #pragma unroll
    for (int mt = 0; mt < 4; ++mt)
        #pragma unroll
        for (int q2 = 0; q2 < 4; ++q2) {
            int r0 = RM + mt * 16 + g;
            int col = j * QC + CN + q2 * 8 + tq * 2;
            *(float2*)(y + (size_t)(b0 + r0) * L + col)     = make_float2(acc[mt][q2][0], acc[mt][q2][1]);
            *(float2*)(y + (size_t)(b0 + r0 + 8) * L + col) = make_float2(acc[mt][q2][2], acc[mt][q2][3]);
        }
}

extern "C" void kernel_launch(void* const* d_in, const int* in_sizes, int n_in,
                              void* d_out, int out_size) {
    const float* u  = (const float*)d_in[0];
    const float* A  = (const float*)d_in[1];
    const float* B  = (const float*)d_in[2];
    const float* C  = (const float*)d_in[3];
    const float* D  = (const float*)d_in[4];
    const float* ls = (const float*)d_in[5];
    float* y = (float*)d_out;

    const int smA0 = 13824 * 4;   // 55296 B
    const int smB  = 18432 * 4;   // 73728 B
    cudaFuncSetAttribute(ssm_a0, cudaFuncAttributeMaxDynamicSharedMemorySize, smA0);
    cudaFuncSetAttribute(ssm_b,  cudaFuncAttributeMaxDynamicSharedMemorySize, smB);

    ssm_gj<<<1, 256>>>(A, B, C, D, ls);
    ssm_mega<<<192, 64>>>();
    ssm_a0<<<1024, 256, smA0>>>(u);
    ssm_a1<<<128, 128>>>();
    ssm_b<<<1024, 256, smB>>>(u, y);
}